// round 7
// baseline (speedup 1.0000x reference)
#include <cuda_runtime.h>
#include <math.h>
#include <cstdint>

#define BB 4
#define QQ 256
#define CCN 1024
#define QDIM 512
#define CDIM 512
#define HH 128

// ---------------- scratch (device globals; no allocation) ----------------
__device__ float g_Ec[BB * CCN * HH];        // e^{2*mc}  (B,C,H)
__device__ float g_Eq[BB * QQ * HH];         // e^{2*mq}  (B,Q,H)
__device__ float g_qpart[BB * QQ * QDIM];    // query @ lo_w[:,512:].T + lo_b
__device__ float g_wc[BB * QQ * CDIM];       // attn @ context
__device__ float g_attn_scratch[BB * QQ * CCN];

#define TWO_LOG2E 2.8853900817779268f

__device__ __forceinline__ float fast_ex2(float x) {
    float e; asm("ex2.approx.f32 %0, %1;" : "=f"(e) : "f"(x)); return e;
}
__device__ __forceinline__ float fast_rcp(float x) {
    float r; asm("rcp.approx.f32 %0, %1;" : "=f"(r) : "f"(x)); return r;
}
__device__ __forceinline__ float fast_tanh(float x) {
    float e = fast_ex2(x * TWO_LOG2E);
    return fmaf(-2.0f, fast_rcp(e + 1.0f), 1.0f);
}

// ---------------- packed f32x2 helpers ----------------
__device__ __forceinline__ void fma2(unsigned long long& acc,
                                     unsigned long long a2,
                                     unsigned long long b2) {
    asm("fma.rn.f32x2 %0, %1, %2, %0;" : "+l"(acc) : "l"(a2), "l"(b2));
}
__device__ __forceinline__ unsigned long long dup2(float a) {
    unsigned long long p;
    asm("mov.b64 %0, {%1, %1};" : "=l"(p) : "r"(__float_as_uint(a)));
    return p;
}
__device__ __forceinline__ void unpack2(unsigned long long p, float& lo, float& hi) {
    uint32_t l, h;
    asm("mov.b64 {%0, %1}, %2;" : "=r"(l), "=r"(h) : "l"(p));
    lo = __uint_as_float(l); hi = __uint_as_float(h);
}

// ---------------- 32x64x16 GEMM core, 128 threads, double-buffered ----------
// A: [M,K] row-major (lda). TRANSB: B is [N,K] (ldb); else [K,N] (ldb).
// epi: 0 = none, 1 = ex2(2*log2e*v), 2 = fast_tanh(v)
// Inner loop: packed fma.rn.f32x2 — 8 FFMA2 + 4 ALU movs per k (vs 16 FFMA).
template <bool TRANSB>
__device__ __forceinline__
void gemm32(const float* __restrict__ A, int lda,
            const float* __restrict__ Bm, int ldb,
            const float* __restrict__ bias,      // nullable
            const float* __restrict__ Add,       // nullable, ldc layout
            float* __restrict__ C, int ldc,
            int K, int m0, int n0, int epi)
{
    __shared__ float As[2][16][32];
    __shared__ float Bs[2][16][64];

    const int tid = threadIdx.x;
    const int tx  = tid & 15;        // n group (x4)
    const int tyr = tid >> 4;        // 0..7 m group (x4)

    const int ar  = tid >> 2;        // 0..31
    const int ac4 = (tid & 3) * 4;   // k sub

    // acc2[i][p]: rows i=0..3, column pair p=0 -> (n+0,n+1), p=1 -> (n+2,n+3)
    unsigned long long acc2[4][2];
    const unsigned long long zero2 = 0ull;   // packed (0.f, 0.f)
#pragma unroll
    for (int i = 0; i < 4; i++) { acc2[i][0] = zero2; acc2[i][1] = zero2; }

    // prefetch tile 0
    float4 av, bv0, bv1;
    av = *(const float4*)&A[(long)(m0 + ar) * lda + ac4];
    if (TRANSB) {
        bv0 = *(const float4*)&Bm[(long)(n0 + ar) * ldb + ac4];
        bv1 = *(const float4*)&Bm[(long)(n0 + 32 + ar) * ldb + ac4];
    } else {
        bv0 = *(const float4*)&Bm[(long)(tid >> 4) * ldb + n0 + (tid & 15) * 4];
        bv1 = *(const float4*)&Bm[(long)(8 + (tid >> 4)) * ldb + n0 + (tid & 15) * 4];
    }

    // store tile 0
    As[0][ac4 + 0][ar] = av.x; As[0][ac4 + 1][ar] = av.y;
    As[0][ac4 + 2][ar] = av.z; As[0][ac4 + 3][ar] = av.w;
    if (TRANSB) {
        Bs[0][ac4 + 0][ar] = bv0.x; Bs[0][ac4 + 1][ar] = bv0.y;
        Bs[0][ac4 + 2][ar] = bv0.z; Bs[0][ac4 + 3][ar] = bv0.w;
        Bs[0][ac4 + 0][32 + ar] = bv1.x; Bs[0][ac4 + 1][32 + ar] = bv1.y;
        Bs[0][ac4 + 2][32 + ar] = bv1.z; Bs[0][ac4 + 3][32 + ar] = bv1.w;
    } else {
        *(float4*)&Bs[0][tid >> 4][(tid & 15) * 4] = bv0;
        *(float4*)&Bs[0][8 + (tid >> 4)][(tid & 15) * 4] = bv1;
    }
    __syncthreads();

    int cur = 0;
    for (int k0 = 0; k0 < K; k0 += 16) {
        const bool more = (k0 + 16) < K;
        if (more) {
            const int kn = k0 + 16;
            av = *(const float4*)&A[(long)(m0 + ar) * lda + kn + ac4];
            if (TRANSB) {
                bv0 = *(const float4*)&Bm[(long)(n0 + ar) * ldb + kn + ac4];
                bv1 = *(const float4*)&Bm[(long)(n0 + 32 + ar) * ldb + kn + ac4];
            } else {
                bv0 = *(const float4*)&Bm[(long)(kn + (tid >> 4)) * ldb + n0 + (tid & 15) * 4];
                bv1 = *(const float4*)&Bm[(long)(kn + 8 + (tid >> 4)) * ldb + n0 + (tid & 15) * 4];
            }
        }

#pragma unroll
        for (int k = 0; k < 16; k++) {
            float4 a = *(const float4*)&As[cur][k][tyr * 4];
            // b pair load: 16B aligned, two packed f32x2 directly
            ulonglong2 bp = *(const ulonglong2*)&Bs[cur][k][tx * 4];
            unsigned long long a0 = dup2(a.x), a1 = dup2(a.y),
                               a2 = dup2(a.z), a3 = dup2(a.w);
            fma2(acc2[0][0], a0, bp.x); fma2(acc2[0][1], a0, bp.y);
            fma2(acc2[1][0], a1, bp.x); fma2(acc2[1][1], a1, bp.y);
            fma2(acc2[2][0], a2, bp.x); fma2(acc2[2][1], a2, bp.y);
            fma2(acc2[3][0], a3, bp.x); fma2(acc2[3][1], a3, bp.y);
        }

        if (more) {
            const int nxt = cur ^ 1;
            As[nxt][ac4 + 0][ar] = av.x; As[nxt][ac4 + 1][ar] = av.y;
            As[nxt][ac4 + 2][ar] = av.z; As[nxt][ac4 + 3][ar] = av.w;
            if (TRANSB) {
                Bs[nxt][ac4 + 0][ar] = bv0.x; Bs[nxt][ac4 + 1][ar] = bv0.y;
                Bs[nxt][ac4 + 2][ar] = bv0.z; Bs[nxt][ac4 + 3][ar] = bv0.w;
                Bs[nxt][ac4 + 0][32 + ar] = bv1.x; Bs[nxt][ac4 + 1][32 + ar] = bv1.y;
                Bs[nxt][ac4 + 2][32 + ar] = bv1.z; Bs[nxt][ac4 + 3][32 + ar] = bv1.w;
            } else {
                *(float4*)&Bs[nxt][tid >> 4][(tid & 15) * 4] = bv0;
                *(float4*)&Bs[nxt][8 + (tid >> 4)][(tid & 15) * 4] = bv1;
            }
        }
        __syncthreads();
        cur ^= 1;
    }

    // epilogue: float4 stores over n
    const int nb = n0 + tx * 4;
    float4 b4 = bias ? *(const float4*)&bias[nb] : make_float4(0.f, 0.f, 0.f, 0.f);
#pragma unroll
    for (int i = 0; i < 4; i++) {
        const int m = m0 + tyr * 4 + i;
        float4 v;
        unpack2(acc2[i][0], v.x, v.y);
        unpack2(acc2[i][1], v.z, v.w);
        v.x += b4.x; v.y += b4.y; v.z += b4.z; v.w += b4.w;
        if (Add) {
            float4 a4 = *(const float4*)&Add[(long)m * ldc + nb];
            v.x += a4.x; v.y += a4.y; v.z += a4.z; v.w += a4.w;
        }
        if (epi == 1) {
            v.x = fast_ex2(v.x * TWO_LOG2E); v.y = fast_ex2(v.y * TWO_LOG2E);
            v.z = fast_ex2(v.z * TWO_LOG2E); v.w = fast_ex2(v.w * TWO_LOG2E);
        } else if (epi == 2) {
            v.x = fast_tanh(v.x); v.y = fast_tanh(v.y);
            v.z = fast_tanh(v.z); v.w = fast_tanh(v.w);
        }
        *(float4*)&C[(long)m * ldc + nb] = v;
    }
}

// ---------------- fused input projections: Ec, Eq, qpart (576 CTAs) --------
__global__ __launch_bounds__(128)
void proj_fused_kernel(const float* __restrict__ context,
                       const float* __restrict__ query,
                       const float* __restrict__ wc_w, const float* __restrict__ wc_b,
                       const float* __restrict__ wq_w, const float* __restrict__ wq_b,
                       const float* __restrict__ lo_w, const float* __restrict__ lo_b,
                       float* __restrict__ Ec, float* __restrict__ Eq,
                       float* __restrict__ qpart)
{
    const int i = blockIdx.x;
    if (i < 256) {               // Ec: 128 m-tiles x 2 n-tiles
        const int m0 = (i >> 1) * 32, n0 = (i & 1) * 64;
        gemm32<true>(context, CDIM, wc_w, CDIM, wc_b, nullptr, Ec, HH,
                     CDIM, m0, n0, 1);
    } else if (i < 320) {        // Eq: 32 x 2
        const int j = i - 256;
        const int m0 = (j >> 1) * 32, n0 = (j & 1) * 64;
        gemm32<true>(query, QDIM, wq_w, QDIM, wq_b, nullptr, Eq, HH,
                     QDIM, m0, n0, 1);
    } else {                     // qpart: 32 x 8
        const int j = i - 320;
        const int m0 = (j >> 3) * 32, n0 = (j & 7) * 64;
        gemm32<true>(query, QDIM, lo_w + CDIM, QDIM + CDIM, lo_b, nullptr,
                     qpart, QDIM, QDIM, m0, n0, 0);
    }
}

// ---------------- wc = attn @ context (256 CTAs) ---------------------------
__global__ __launch_bounds__(128)
void gemm_nn_kernel(const float* __restrict__ attn,
                    const float* __restrict__ context,
                    float* __restrict__ wc)
{
    const int b = blockIdx.z;
    gemm32<false>(attn + (long)b * QQ * CCN, CCN,
                  context + (long)b * CCN * CDIM, CDIM,
                  nullptr, nullptr,
                  wc + (long)b * QQ * CDIM, CDIM,
                  CCN, blockIdx.y * 32, blockIdx.x * 64, 0);
}

// ---------------- out = tanh(wc @ lo_w[:,:512].T + qpart) (256 CTAs) -------
__global__ __launch_bounds__(128)
void gemm_out_kernel(const float* __restrict__ wc,
                     const float* __restrict__ lo_w,
                     const float* __restrict__ qpart,
                     float* __restrict__ out)
{
    gemm32<true>(wc, CDIM, lo_w, QDIM + CDIM, nullptr, qpart,
                 out, QDIM, CDIM, blockIdx.y * 32, blockIdx.x * 64, 2);
}

// ---------------- emission + masked softmax ----------------
#define QT 4
#define CH 32
#define NCHUNK (CCN / CH)
#define ECPAD 132

__global__ __launch_bounds__(128)
void emission_softmax2(const float* __restrict__ Ec,
                       const float* __restrict__ Eq,
                       const int* __restrict__ mask,
                       const float* __restrict__ we_w,
                       const float* __restrict__ we_b,
                       float* __restrict__ attn)
{
    __shared__ float ecs[CH][ECPAD];
    __shared__ float eqs[QT][HH];
    __shared__ float wes[HH];
    __shared__ int ms[CH];

    const int b  = blockIdx.y;
    const int q0 = blockIdx.x * QT;
    const int tid = threadIdx.x;
    const int lane = tid & 31;
    const int q = tid >> 5;

    if (tid < HH) wes[tid] = we_w[tid];
    {
        const float4* src = (const float4*)&Eq[(long)(b * QQ + q0) * HH];
        float4* dst = (float4*)&eqs[0][0];
        for (int i = tid; i < QT * HH / 4; i += 128) dst[i] = src[i];
    }
    __syncthreads();

    float W = 0.f;
#pragma unroll
    for (int h = 0; h < HH; h += 4) {
        float4 w4 = *(const float4*)&wes[h];
        W += (w4.x + w4.y) + (w4.z + w4.w);
    }
    const float eb = we_b[0];

    float es_l[NCHUNK];

    for (int ch = 0; ch < NCHUNK; ch++) {
        __syncthreads();
        {
            const float4* src = (const float4*)&Ec[((long)b * CCN + ch * CH) * HH];
            for (int i = tid; i < CH * HH / 4; i += 128) {
                int r  = i >> 5;
                int c4 = (i & 31) * 4;
                *(float4*)&ecs[r][c4] = src[i];
            }
            if (tid < CH) ms[tid] = mask[b * CCN + ch * CH + tid];
        }
        __syncthreads();

        float s0 = 0.f, s1 = 0.f;
#pragma unroll
        for (int h = 0; h < HH; h += 8) {
            float4 e0 = *(const float4*)&ecs[lane][h];
            float4 g0 = *(const float4*)&eqs[q][h];
            float4 w0 = *(const float4*)&wes[h];
            float4 e1 = *(const float4*)&ecs[lane][h + 4];
            float4 g1 = *(const float4*)&eqs[q][h + 4];
            float4 w1 = *(const float4*)&wes[h + 4];
            s0 += w0.x * fast_rcp(fmaf(e0.x, g0.x, 1.f));
            s1 += w0.y * fast_rcp(fmaf(e0.y, g0.y, 1.f));
            s0 += w0.z * fast_rcp(fmaf(e0.z, g0.z, 1.f));
            s1 += w0.w * fast_rcp(fmaf(e0.w, g0.w, 1.f));
            s0 += w1.x * fast_rcp(fmaf(e1.x, g1.x, 1.f));
            s1 += w1.y * fast_rcp(fmaf(e1.y, g1.y, 1.f));
            s0 += w1.z * fast_rcp(fmaf(e1.z, g1.z, 1.f));
            s1 += w1.w * fast_rcp(fmaf(e1.w, g1.w, 1.f));
        }
        float s = s0 + s1;
        es_l[ch] = ms[lane] ? (fmaf(-2.f, s, W) + eb) : -INFINITY;
    }

    float lm = -INFINITY;
#pragma unroll
    for (int ch = 0; ch < NCHUNK; ch++) lm = fmaxf(lm, es_l[ch]);
#pragma unroll
    for (int off = 16; off >= 1; off >>= 1)
        lm = fmaxf(lm, __shfl_xor_sync(0xffffffffu, lm, off));
    const bool ok = (lm > -3.0e38f);

    float ls = 0.f;
#pragma unroll
    for (int ch = 0; ch < NCHUNK; ch++) {
        float e = ok ? __expf(es_l[ch] - lm) : 0.f;
        es_l[ch] = e;
        ls += e;
    }
#pragma unroll
    for (int off = 16; off >= 1; off >>= 1)
        ls += __shfl_xor_sync(0xffffffffu, ls, off);
    const float inv = (ls > 0.f) ? 1.f / ls : 0.f;

    float* arow = attn + (long)(b * QQ + q0 + q) * CCN;
#pragma unroll
    for (int ch = 0; ch < NCHUNK; ch++) arow[ch * CH + lane] = es_l[ch] * inv;
}

// ---------------- launcher ----------------
extern "C" void kernel_launch(void* const* d_in, const int* in_sizes, int n_in,
                              void* d_out, int out_size)
{
    const float* query   = (const float*)d_in[0];
    const float* context = (const float*)d_in[1];
    const int*   mask    = (const int*)d_in[2];
    const float* wq_w = (const float*)d_in[3];
    const float* wq_b = (const float*)d_in[4];
    const float* wc_w = (const float*)d_in[5];
    const float* wc_b = (const float*)d_in[6];
    const float* we_w = (const float*)d_in[7];
    const float* we_b = (const float*)d_in[8];
    const float* lo_w = (const float*)d_in[9];
    const float* lo_b = (const float*)d_in[10];

    float *Ec, *Eq, *qpart, *wc, *attn_s;
    cudaGetSymbolAddress((void**)&Ec, g_Ec);
    cudaGetSymbolAddress((void**)&Eq, g_Eq);
    cudaGetSymbolAddress((void**)&qpart, g_qpart);
    cudaGetSymbolAddress((void**)&wc, g_wc);
    cudaGetSymbolAddress((void**)&attn_s, g_attn_scratch);

    const int nOut  = BB * QQ * QDIM;
    const int nAttn = BB * QQ * CCN;
    float* outPtr  = nullptr;
    float* attnPtr = nullptr;
    if (out_size >= nOut + nAttn) {
        outPtr  = (float*)d_out;
        attnPtr = (float*)d_out + nOut;
    } else if (out_size == nAttn) {
        attnPtr = (float*)d_out;
    } else {
        outPtr = (float*)d_out;
    }
    if (!attnPtr) attnPtr = attn_s;

    // 1) all input-only projections in one launch: Ec, Eq, qpart (576 CTAs)
    proj_fused_kernel<<<576, 128>>>(context, query, wc_w, wc_b, wq_w, wq_b,
                                    lo_w, lo_b, Ec, Eq, qpart);

    // 2) emission + softmax -> attn (256 CTAs)
    emission_softmax2<<<dim3(QQ / QT, BB), 128>>>(Ec, Eq, mask, we_w, we_b, attnPtr);

    if (outPtr) {
        // 3) wc = attn @ context (256 CTAs)
        gemm_nn_kernel<<<dim3(CDIM / 64, QQ / 32, BB), 128>>>(attnPtr, context, wc);

        // 4) out = tanh(wc @ lo_w[:,:512].T + qpart) (256 CTAs)
        gemm_out_kernel<<<dim3(QDIM / 64, BB * QQ / 32), 128>>>(wc, lo_w, qpart, outPtr);
    }
}

// round 8
// speedup vs baseline: 1.0003x; 1.0003x over previous
#include <cuda_runtime.h>
#include <math.h>
#include <cstdint>

#define BB 4
#define QQ 256
#define CCN 1024
#define QDIM 512
#define CDIM 512
#define HH 128

// ---------------- scratch (device globals; no allocation) ----------------
__device__ float g_Ec[BB * CCN * HH];        // e^{2*mc}  (B,C,H)
__device__ float g_Eq[BB * QQ * HH];         // e^{2*mq}  (B,Q,H)
__device__ float g_qpart[BB * QQ * QDIM];    // query @ lo_w[:,512:].T + lo_b
__device__ float g_wc[BB * QQ * CDIM];       // attn @ context
__device__ float g_attn_scratch[BB * QQ * CCN];

#define TWO_LOG2E 2.8853900817779268f

__device__ __forceinline__ float fast_ex2(float x) {
    float e; asm("ex2.approx.f32 %0, %1;" : "=f"(e) : "f"(x)); return e;
}
__device__ __forceinline__ float fast_rcp(float x) {
    float r; asm("rcp.approx.f32 %0, %1;" : "=f"(r) : "f"(x)); return r;
}
__device__ __forceinline__ float fast_tanh(float x) {
    float e = fast_ex2(x * TWO_LOG2E);
    return fmaf(-2.0f, fast_rcp(e + 1.0f), 1.0f);
}

// ---------------- packed f32x2 helpers ----------------
__device__ __forceinline__ void fma2(unsigned long long& acc,
                                     unsigned long long a2,
                                     unsigned long long b2) {
    asm("fma.rn.f32x2 %0, %1, %2, %0;" : "+l"(acc) : "l"(a2), "l"(b2));
}
__device__ __forceinline__ unsigned long long dup2(float a) {
    unsigned long long p;
    asm("mov.b64 %0, {%1, %1};" : "=l"(p) : "r"(__float_as_uint(a)));
    return p;
}
__device__ __forceinline__ void unpack2(unsigned long long p, float& lo, float& hi) {
    uint32_t l, h;
    asm("mov.b64 {%0, %1}, %2;" : "=r"(l), "=r"(h) : "l"(p));
    lo = __uint_as_float(l); hi = __uint_as_float(h);
}

// ---------------- 32x64 tile GEMM, 512 threads, 4-way intra-CTA split-K -----
// A: [M,K] row-major (lda). TRANSB: B is [N,K] (ldb); else [K,N] (ldb).
// Each 128-thread group g handles k in [g*K/4, (g+1)*K/4) with its own
// double-buffered staging; partials reduced through smem at the end.
// Requires K % 64 == 0 (so K/4 is a multiple of 16).
// epi: 0 = none, 1 = ex2(2*log2e*v), 2 = fast_tanh(v)
template <bool TRANSB>
__device__ __forceinline__
void gemm_splitk(const float* __restrict__ A, int lda,
                 const float* __restrict__ Bm, int ldb,
                 const float* __restrict__ bias,      // nullable
                 const float* __restrict__ Add,       // nullable, ldc layout
                 float* __restrict__ C, int ldc,
                 int K, int m0, int n0, int epi)
{
    // per group: As 2*16*32 = 1024 floats, Bs 2*16*64 = 2048 floats
    __shared__ float sp[4 * 3072];   // 48KB exactly; aliased by reduction

    const int tid = threadIdx.x;
    const int g   = tid >> 7;        // k-group 0..3
    const int t   = tid & 127;       // thread within group
    const int tx  = t & 15;          // n group (x4)
    const int tyr = t >> 4;          // 0..7 m group (x4)
    const int ar  = t >> 2;          // 0..31
    const int ac4 = (t & 3) * 4;     // k sub

    float* const Ag = sp + g * 3072;          // [buf][k][32]
    float* const Bg = sp + g * 3072 + 1024;   // [buf][k][64]

    const int kq   = K >> 2;
    const int kbeg = g * kq;
    const int kend = kbeg + kq;

    unsigned long long acc2[4][2];
#pragma unroll
    for (int i = 0; i < 4; i++) { acc2[i][0] = 0ull; acc2[i][1] = 0ull; }

    // prefetch first tile of this group's k-range
    float4 av, bv0, bv1;
    av = *(const float4*)&A[(long)(m0 + ar) * lda + kbeg + ac4];
    if (TRANSB) {
        bv0 = *(const float4*)&Bm[(long)(n0 + ar) * ldb + kbeg + ac4];
        bv1 = *(const float4*)&Bm[(long)(n0 + 32 + ar) * ldb + kbeg + ac4];
    } else {
        bv0 = *(const float4*)&Bm[(long)(kbeg + (t >> 4)) * ldb + n0 + (t & 15) * 4];
        bv1 = *(const float4*)&Bm[(long)(kbeg + 8 + (t >> 4)) * ldb + n0 + (t & 15) * 4];
    }

    // store tile 0
    Ag[(ac4 + 0) * 32 + ar] = av.x; Ag[(ac4 + 1) * 32 + ar] = av.y;
    Ag[(ac4 + 2) * 32 + ar] = av.z; Ag[(ac4 + 3) * 32 + ar] = av.w;
    if (TRANSB) {
        Bg[(ac4 + 0) * 64 + ar] = bv0.x; Bg[(ac4 + 1) * 64 + ar] = bv0.y;
        Bg[(ac4 + 2) * 64 + ar] = bv0.z; Bg[(ac4 + 3) * 64 + ar] = bv0.w;
        Bg[(ac4 + 0) * 64 + 32 + ar] = bv1.x; Bg[(ac4 + 1) * 64 + 32 + ar] = bv1.y;
        Bg[(ac4 + 2) * 64 + 32 + ar] = bv1.z; Bg[(ac4 + 3) * 64 + 32 + ar] = bv1.w;
    } else {
        *(float4*)&Bg[(t >> 4) * 64 + (t & 15) * 4] = bv0;
        *(float4*)&Bg[(8 + (t >> 4)) * 64 + (t & 15) * 4] = bv1;
    }
    __syncthreads();

    int cur = 0;
    for (int k0 = kbeg; k0 < kend; k0 += 16) {
        const bool more = (k0 + 16) < kend;      // identical across groups
        if (more) {
            const int kn = k0 + 16;
            av = *(const float4*)&A[(long)(m0 + ar) * lda + kn + ac4];
            if (TRANSB) {
                bv0 = *(const float4*)&Bm[(long)(n0 + ar) * ldb + kn + ac4];
                bv1 = *(const float4*)&Bm[(long)(n0 + 32 + ar) * ldb + kn + ac4];
            } else {
                bv0 = *(const float4*)&Bm[(long)(kn + (t >> 4)) * ldb + n0 + (t & 15) * 4];
                bv1 = *(const float4*)&Bm[(long)(kn + 8 + (t >> 4)) * ldb + n0 + (t & 15) * 4];
            }
        }

        float* const Ac = Ag + cur * 512;
        float* const Bc = Bg + cur * 1024;
#pragma unroll
        for (int k = 0; k < 16; k++) {
            float4 a = *(const float4*)&Ac[k * 32 + tyr * 4];
            ulonglong2 bp = *(const ulonglong2*)&Bc[k * 64 + tx * 4];
            unsigned long long a0 = dup2(a.x), a1 = dup2(a.y),
                               a2 = dup2(a.z), a3 = dup2(a.w);
            fma2(acc2[0][0], a0, bp.x); fma2(acc2[0][1], a0, bp.y);
            fma2(acc2[1][0], a1, bp.x); fma2(acc2[1][1], a1, bp.y);
            fma2(acc2[2][0], a2, bp.x); fma2(acc2[2][1], a2, bp.y);
            fma2(acc2[3][0], a3, bp.x); fma2(acc2[3][1], a3, bp.y);
        }

        if (more) {
            const int nxt = cur ^ 1;
            float* const An = Ag + nxt * 512;
            float* const Bn = Bg + nxt * 1024;
            An[(ac4 + 0) * 32 + ar] = av.x; An[(ac4 + 1) * 32 + ar] = av.y;
            An[(ac4 + 2) * 32 + ar] = av.z; An[(ac4 + 3) * 32 + ar] = av.w;
            if (TRANSB) {
                Bn[(ac4 + 0) * 64 + ar] = bv0.x; Bn[(ac4 + 1) * 64 + ar] = bv0.y;
                Bn[(ac4 + 2) * 64 + ar] = bv0.z; Bn[(ac4 + 3) * 64 + ar] = bv0.w;
                Bn[(ac4 + 0) * 64 + 32 + ar] = bv1.x; Bn[(ac4 + 1) * 64 + 32 + ar] = bv1.y;
                Bn[(ac4 + 2) * 64 + 32 + ar] = bv1.z; Bn[(ac4 + 3) * 64 + 32 + ar] = bv1.w;
            } else {
                *(float4*)&Bn[(t >> 4) * 64 + (t & 15) * 4] = bv0;
                *(float4*)&Bn[(8 + (t >> 4)) * 64 + (t & 15) * 4] = bv1;
            }
        }
        __syncthreads();
        cur ^= 1;
    }

    // ---- cross-group reduction through smem (aliases staging) ----
    float* const red = sp;           // [4][2048]
    float* const myred = red + g * 2048;
#pragma unroll
    for (int i = 0; i < 4; i++) {
        float4 v;
        unpack2(acc2[i][0], v.x, v.y);
        unpack2(acc2[i][1], v.z, v.w);
        *(float4*)&myred[(tyr * 4 + i) * 64 + tx * 4] = v;
    }
    __syncthreads();

    // each thread reduces + finishes 4 consecutive outputs
    const int idx = tid * 4;                 // 0..2044
    float4 v0 = *(const float4*)&red[idx];
    float4 v1 = *(const float4*)&red[2048 + idx];
    float4 v2 = *(const float4*)&red[4096 + idx];
    float4 v3 = *(const float4*)&red[6144 + idx];
    float4 v = make_float4((v0.x + v1.x) + (v2.x + v3.x),
                           (v0.y + v1.y) + (v2.y + v3.y),
                           (v0.z + v1.z) + (v2.z + v3.z),
                           (v0.w + v1.w) + (v2.w + v3.w));

    const int m  = m0 + (idx >> 6);
    const int nb = n0 + (idx & 63);
    if (bias) {
        float4 b4 = *(const float4*)&bias[nb];
        v.x += b4.x; v.y += b4.y; v.z += b4.z; v.w += b4.w;
    }
    if (Add) {
        float4 a4 = *(const float4*)&Add[(long)m * ldc + nb];
        v.x += a4.x; v.y += a4.y; v.z += a4.z; v.w += a4.w;
    }
    if (epi == 1) {
        v.x = fast_ex2(v.x * TWO_LOG2E); v.y = fast_ex2(v.y * TWO_LOG2E);
        v.z = fast_ex2(v.z * TWO_LOG2E); v.w = fast_ex2(v.w * TWO_LOG2E);
    } else if (epi == 2) {
        v.x = fast_tanh(v.x); v.y = fast_tanh(v.y);
        v.z = fast_tanh(v.z); v.w = fast_tanh(v.w);
    }
    *(float4*)&C[(long)m * ldc + nb] = v;
}

// ---------------- fused input projections: Ec, Eq, qpart (576 CTAs) --------
__global__ __launch_bounds__(512)
void proj_fused_kernel(const float* __restrict__ context,
                       const float* __restrict__ query,
                       const float* __restrict__ wc_w, const float* __restrict__ wc_b,
                       const float* __restrict__ wq_w, const float* __restrict__ wq_b,
                       const float* __restrict__ lo_w, const float* __restrict__ lo_b,
                       float* __restrict__ Ec, float* __restrict__ Eq,
                       float* __restrict__ qpart)
{
    const int i = blockIdx.x;
    if (i < 256) {               // Ec: 128 m-tiles x 2 n-tiles
        const int m0 = (i >> 1) * 32, n0 = (i & 1) * 64;
        gemm_splitk<true>(context, CDIM, wc_w, CDIM, wc_b, nullptr, Ec, HH,
                          CDIM, m0, n0, 1);
    } else if (i < 320) {        // Eq: 32 x 2
        const int j = i - 256;
        const int m0 = (j >> 1) * 32, n0 = (j & 1) * 64;
        gemm_splitk<true>(query, QDIM, wq_w, QDIM, wq_b, nullptr, Eq, HH,
                          QDIM, m0, n0, 1);
    } else {                     // qpart: 32 x 8
        const int j = i - 320;
        const int m0 = (j >> 3) * 32, n0 = (j & 7) * 64;
        gemm_splitk<true>(query, QDIM, lo_w + CDIM, QDIM + CDIM, lo_b, nullptr,
                          qpart, QDIM, QDIM, m0, n0, 0);
    }
}

// ---------------- wc = attn @ context (256 CTAs) ---------------------------
__global__ __launch_bounds__(512)
void gemm_nn_kernel(const float* __restrict__ attn,
                    const float* __restrict__ context,
                    float* __restrict__ wc)
{
    const int b = blockIdx.z;
    gemm_splitk<false>(attn + (long)b * QQ * CCN, CCN,
                       context + (long)b * CCN * CDIM, CDIM,
                       nullptr, nullptr,
                       wc + (long)b * QQ * CDIM, CDIM,
                       CCN, blockIdx.y * 32, blockIdx.x * 64, 0);
}

// ---------------- out = tanh(wc @ lo_w[:,:512].T + qpart) (256 CTAs) -------
__global__ __launch_bounds__(512)
void gemm_out_kernel(const float* __restrict__ wc,
                     const float* __restrict__ lo_w,
                     const float* __restrict__ qpart,
                     float* __restrict__ out)
{
    gemm_splitk<true>(wc, CDIM, lo_w, QDIM + CDIM, nullptr, qpart,
                      out, QDIM, CDIM, blockIdx.y * 32, blockIdx.x * 64, 2);
}

// ---------------- emission + masked softmax (unchanged) ----------------
#define QT 4
#define CH 32
#define NCHUNK (CCN / CH)
#define ECPAD 132

__global__ __launch_bounds__(128)
void emission_softmax2(const float* __restrict__ Ec,
                       const float* __restrict__ Eq,
                       const int* __restrict__ mask,
                       const float* __restrict__ we_w,
                       const float* __restrict__ we_b,
                       float* __restrict__ attn)
{
    __shared__ float ecs[CH][ECPAD];
    __shared__ float eqs[QT][HH];
    __shared__ float wes[HH];
    __shared__ int ms[CH];

    const int b  = blockIdx.y;
    const int q0 = blockIdx.x * QT;
    const int tid = threadIdx.x;
    const int lane = tid & 31;
    const int q = tid >> 5;

    if (tid < HH) wes[tid] = we_w[tid];
    {
        const float4* src = (const float4*)&Eq[(long)(b * QQ + q0) * HH];
        float4* dst = (float4*)&eqs[0][0];
        for (int i = tid; i < QT * HH / 4; i += 128) dst[i] = src[i];
    }
    __syncthreads();

    float W = 0.f;
#pragma unroll
    for (int h = 0; h < HH; h += 4) {
        float4 w4 = *(const float4*)&wes[h];
        W += (w4.x + w4.y) + (w4.z + w4.w);
    }
    const float eb = we_b[0];

    float es_l[NCHUNK];

    for (int ch = 0; ch < NCHUNK; ch++) {
        __syncthreads();
        {
            const float4* src = (const float4*)&Ec[((long)b * CCN + ch * CH) * HH];
            for (int i = tid; i < CH * HH / 4; i += 128) {
                int r  = i >> 5;
                int c4 = (i & 31) * 4;
                *(float4*)&ecs[r][c4] = src[i];
            }
            if (tid < CH) ms[tid] = mask[b * CCN + ch * CH + tid];
        }
        __syncthreads();

        float s0 = 0.f, s1 = 0.f;
#pragma unroll
        for (int h = 0; h < HH; h += 8) {
            float4 e0 = *(const float4*)&ecs[lane][h];
            float4 g0 = *(const float4*)&eqs[q][h];
            float4 w0 = *(const float4*)&wes[h];
            float4 e1 = *(const float4*)&ecs[lane][h + 4];
            float4 g1 = *(const float4*)&eqs[q][h + 4];
            float4 w1 = *(const float4*)&wes[h + 4];
            s0 += w0.x * fast_rcp(fmaf(e0.x, g0.x, 1.f));
            s1 += w0.y * fast_rcp(fmaf(e0.y, g0.y, 1.f));
            s0 += w0.z * fast_rcp(fmaf(e0.z, g0.z, 1.f));
            s1 += w0.w * fast_rcp(fmaf(e0.w, g0.w, 1.f));
            s0 += w1.x * fast_rcp(fmaf(e1.x, g1.x, 1.f));
            s1 += w1.y * fast_rcp(fmaf(e1.y, g1.y, 1.f));
            s0 += w1.z * fast_rcp(fmaf(e1.z, g1.z, 1.f));
            s1 += w1.w * fast_rcp(fmaf(e1.w, g1.w, 1.f));
        }
        float s = s0 + s1;
        es_l[ch] = ms[lane] ? (fmaf(-2.f, s, W) + eb) : -INFINITY;
    }

    float lm = -INFINITY;
#pragma unroll
    for (int ch = 0; ch < NCHUNK; ch++) lm = fmaxf(lm, es_l[ch]);
#pragma unroll
    for (int off = 16; off >= 1; off >>= 1)
        lm = fmaxf(lm, __shfl_xor_sync(0xffffffffu, lm, off));
    const bool ok = (lm > -3.0e38f);

    float ls = 0.f;
#pragma unroll
    for (int ch = 0; ch < NCHUNK; ch++) {
        float e = ok ? __expf(es_l[ch] - lm) : 0.f;
        es_l[ch] = e;
        ls += e;
    }
#pragma unroll
    for (int off = 16; off >= 1; off >>= 1)
        ls += __shfl_xor_sync(0xffffffffu, ls, off);
    const float inv = (ls > 0.f) ? 1.f / ls : 0.f;

    float* arow = attn + (long)(b * QQ + q0 + q) * CCN;
#pragma unroll
    for (int ch = 0; ch < NCHUNK; ch++) arow[ch * CH + lane] = es_l[ch] * inv;
}

// ---------------- launcher ----------------
extern "C" void kernel_launch(void* const* d_in, const int* in_sizes, int n_in,
                              void* d_out, int out_size)
{
    const float* query   = (const float*)d_in[0];
    const float* context = (const float*)d_in[1];
    const int*   mask    = (const int*)d_in[2];
    const float* wq_w = (const float*)d_in[3];
    const float* wq_b = (const float*)d_in[4];
    const float* wc_w = (const float*)d_in[5];
    const float* wc_b = (const float*)d_in[6];
    const float* we_w = (const float*)d_in[7];
    const float* we_b = (const float*)d_in[8];
    const float* lo_w = (const float*)d_in[9];
    const float* lo_b = (const float*)d_in[10];

    float *Ec, *Eq, *qpart, *wc, *attn_s;
    cudaGetSymbolAddress((void**)&Ec, g_Ec);
    cudaGetSymbolAddress((void**)&Eq, g_Eq);
    cudaGetSymbolAddress((void**)&qpart, g_qpart);
    cudaGetSymbolAddress((void**)&wc, g_wc);
    cudaGetSymbolAddress((void**)&attn_s, g_attn_scratch);

    const int nOut  = BB * QQ * QDIM;
    const int nAttn = BB * QQ * CCN;
    float* outPtr  = nullptr;
    float* attnPtr = nullptr;
    if (out_size >= nOut + nAttn) {
        outPtr  = (float*)d_out;
        attnPtr = (float*)d_out + nOut;
    } else if (out_size == nAttn) {
        attnPtr = (float*)d_out;
    } else {
        outPtr = (float*)d_out;
    }
    if (!attnPtr) attnPtr = attn_s;

    // 1) all input-only projections in one launch: Ec, Eq, qpart (576 CTAs)
    proj_fused_kernel<<<576, 512>>>(context, query, wc_w, wc_b, wq_w, wq_b,
                                    lo_w, lo_b, Ec, Eq, qpart);

    // 2) emission + softmax -> attn (256 CTAs)
    emission_softmax2<<<dim3(QQ / QT, BB), 128>>>(Ec, Eq, mask, we_w, we_b, attnPtr);

    if (outPtr) {
        // 3) wc = attn @ context (256 CTAs)
        gemm_nn_kernel<<<dim3(CDIM / 64, QQ / 32, BB), 512>>>(attnPtr, context, wc);

        // 4) out = tanh(wc @ lo_w[:,:512].T + qpart) (256 CTAs)
        gemm_out_kernel<<<dim3(QDIM / 64, BB * QQ / 32), 512>>>(wc, lo_w, qpart, outPtr);
    }
}